// round 15
// baseline (speedup 1.0000x reference)
#include <cuda_runtime.h>
#include <cuda_bf16.h>
#include <cuda_fp16.h>
#include <math.h>
#include <float.h>
#include <cstdint>

#define BB 8192
#define DD 1024
#define NN 4096
#define LRC 0.02f
#define ATC 0.3f
#define ACOEF 0.002f
#define EPSDS 0.5f
#define MARGIN 2e-3f
#define CAND_CAP (1 << 16)
#define HMMA_TILES 53   // M tiles via tensor path; rest via FFMA path

// ---------------- device scratch ----------------
__device__ unsigned long long g_best[BB];
__device__ float g_x2[BB];
__device__ float g_w2[NN];
__device__ float g_rsum[NN];
__device__ float g_counts[NN];
__device__ unsigned int g_rowmax[BB];
__device__ int g_ncand;
__device__ unsigned int g_cand[CAND_CAP];
__device__ __nv_bfloat16 g_xb[BB * DD];       // 16 MB
__device__ __nv_bfloat16 g_wb[NN * DD];       // 8 MB
__device__ __half g_acth[(size_t)BB * NN];    // 32 MB fp16 acts

__device__ __forceinline__ uint32_t smem_u32(const void* p) {
    uint32_t a;
    asm("{ .reg .u64 t; cvta.to.shared.u64 t, %1; cvt.u32.u64 %0, t; }" : "=r"(a) : "l"(p));
    return a;
}

#define LDSM4(r0, r1, r2, r3, addr) \
    asm volatile("ldmatrix.sync.aligned.m8n8.x4.shared.b16 {%0,%1,%2,%3}, [%4];" \
                 : "=r"(r0), "=r"(r1), "=r"(r2), "=r"(r3) : "r"(addr))
#define MMA16816(c0, c1, c2, c3, a0, a1, a2, a3, b0, b1) \
    asm volatile("mma.sync.aligned.m16n8k16.row.col.f32.bf16.bf16.f32 " \
                 "{%0,%1,%2,%3}, {%4,%5,%6,%7}, {%8,%9}, {%0,%1,%2,%3};" \
                 : "+f"(c0), "+f"(c1), "+f"(c2), "+f"(c3) \
                 : "r"(a0), "r"(a1), "r"(a2), "r"(a3), "r"(b0), "r"(b1))
#define CPASYNC16(dst, src) \
    asm volatile("cp.async.ca.shared.global [%0], [%1], 16;" :: "r"(dst), "l"(src))
#define CPCOMMIT() asm volatile("cp.async.commit_group;" ::: "memory")
#define CPWAIT1() asm volatile("cp.async.wait_group 1;" ::: "memory")

static constexpr int STAGE_B = 24576;
static constexpr int GEMM_SMEM = 3 * STAGE_B;   // 73728 (FFMA path uses 32KB of it)

// ---------------------------------------------------------------------------
// K0: zero sums region + counters
// ---------------------------------------------------------------------------
__global__ void k_init(float4* __restrict__ sums4) {
    int i = blockIdx.x * blockDim.x + threadIdx.x;
    sums4[i] = make_float4(0.f, 0.f, 0.f, 0.f);
    if (i < NN) g_counts[i] = 0.f;
    if (i < BB) { g_rowmax[i] = 0u; g_best[i] = 0ull; }
    if (i == 0) g_ncand = 0;
}

// ---------------------------------------------------------------------------
// K1: row reductions + bf16 conversion (warp per row)
// ---------------------------------------------------------------------------
__global__ void __launch_bounds__(256)
k_rowprep(const float* __restrict__ X, const float* __restrict__ W,
          const float* __restrict__ REL) {
    const int wid = threadIdx.x >> 5, l = threadIdx.x & 31;
    const int r = blockIdx.x * 8 + wid;
    float v1 = 0.f, v2 = 0.f;
    if (r < BB) {
        const float4* xr = (const float4*)(X + (size_t)r * DD);
        uint2* ob = (uint2*)(g_xb + (size_t)r * DD);
#pragma unroll
        for (int j = 0; j < 8; j++) {
            float4 v = xr[l + j * 32];
            v1 += v.x * v.x + v.y * v.y + v.z * v.z + v.w * v.w;
            __nv_bfloat162 p0 = __floats2bfloat162_rn(v.x, v.y);
            __nv_bfloat162 p1 = __floats2bfloat162_rn(v.z, v.w);
            ob[l + j * 32] = make_uint2(*(uint32_t*)&p0, *(uint32_t*)&p1);
        }
    } else {
        const int n = r - BB;
        const float4* wr = (const float4*)(W + (size_t)n * DD);
        const float4* rr = (const float4*)(REL + (size_t)n * DD);
        uint2* ob = (uint2*)(g_wb + (size_t)n * DD);
#pragma unroll
        for (int j = 0; j < 8; j++) {
            float4 v = wr[l + j * 32];
            float4 rv = rr[l + j * 32];
            v1 += v.x * v.x + v.y * v.y + v.z * v.z + v.w * v.w;
            v2 += rv.x + rv.y + rv.z + rv.w;
            __nv_bfloat162 p0 = __floats2bfloat162_rn(v.x, v.y);
            __nv_bfloat162 p1 = __floats2bfloat162_rn(v.z, v.w);
            ob[l + j * 32] = make_uint2(*(uint32_t*)&p0, *(uint32_t*)&p1);
        }
    }
#pragma unroll
    for (int o = 16; o > 0; o >>= 1) {
        v1 += __shfl_down_sync(0xFFFFFFFFu, v1, o);
        v2 += __shfl_down_sync(0xFFFFFFFFu, v2, o);
    }
    if (l == 0) {
        if (r < BB) g_x2[r] = v1;
        else { g_w2[r - BB] = v1; g_rsum[r - BB] = v2; }
    }
}

// ---------------------------------------------------------------------------
// K2: mixed GEMM. blockIdx.y < HMMA_TILES -> bf16 mma.sync path;
//     else fp32 SIMT FFMA path. Both: act -> fp16 g_acth + rowmax.
// ---------------------------------------------------------------------------
__global__ void __launch_bounds__(256, 2)
k_gemm_mixed(const float* __restrict__ NC, const float* __restrict__ X,
             const float* __restrict__ W) {
    extern __shared__ __align__(128) char sm[];
    const uint32_t sb = smem_u32(sm);

    const int tid = threadIdx.x;
    const int l = tid & 31, wid = tid >> 5;
    const int mBase = blockIdx.y * 128;
    const int nBase = blockIdx.x * 128;

    if (blockIdx.y < HMMA_TILES) {
        // ================= HMMA path (R13 GEMM) =================
        const int warp_m = wid >> 2, warp_n = wid & 3;
        const int row = tid >> 1, h = tid & 1;
        const __nv_bfloat16* xg = g_xb + (size_t)(mBase + row) * DD + h * 16;
        const __nv_bfloat16* wg = g_wb + (size_t)(nBase + row) * DD + h * 16;
        const uint32_t aDst = sb + h * 6144 + row * 48;
        const uint32_t bDst = sb + 12288 + h * 6144 + row * 48;

#pragma unroll
        for (int s = 0; s < 2; s++) {
            const __nv_bfloat16* xs = xg + s * 32;
            const __nv_bfloat16* ws = wg + s * 32;
            CPASYNC16(aDst + s * STAGE_B, xs);
            CPASYNC16(aDst + s * STAGE_B + 16, xs + 8);
            CPASYNC16(bDst + s * STAGE_B, ws);
            CPASYNC16(bDst + s * STAGE_B + 16, ws + 8);
            CPCOMMIT();
        }

        float c[4][4][4];
#pragma unroll
        for (int i = 0; i < 4; i++)
#pragma unroll
            for (int j = 0; j < 4; j++)
#pragma unroll
                for (int k = 0; k < 4; k++) c[i][j][k] = 0.f;

        const uint32_t aAddr0 = sb + (warp_m * 64 + (l & 15)) * 48 + (l >> 4) * 16;
        const int b_nt_off = (l >> 4) & 1;
        const int b_half = (l >> 3) & 1;
        const uint32_t bAddr0 = sb + 12288 +
            (warp_n * 32 + b_nt_off * 8 + (l & 7)) * 48 + b_half * 16;

        for (int kt = 0; kt < 32; kt++) {
            CPWAIT1();
            __syncthreads();
            if (kt + 2 < 32) {
                const int s = (kt + 2) % 3;
                const __nv_bfloat16* xs = xg + (kt + 2) * 32;
                const __nv_bfloat16* ws = wg + (kt + 2) * 32;
                CPASYNC16(aDst + s * STAGE_B, xs);
                CPASYNC16(aDst + s * STAGE_B + 16, xs + 8);
                CPASYNC16(bDst + s * STAGE_B, ws);
                CPASYNC16(bDst + s * STAGE_B + 16, ws + 8);
            }
            CPCOMMIT();

            const uint32_t aB = aAddr0 + (kt % 3) * STAGE_B;
            const uint32_t bB = bAddr0 + (kt % 3) * STAGE_B;
#pragma unroll
            for (int ch = 0; ch < 2; ch++) {
                uint32_t a[4][4], b[4][2];
#pragma unroll
                for (int mt = 0; mt < 4; mt++)
                    LDSM4(a[mt][0], a[mt][1], a[mt][2], a[mt][3],
                          aB + ch * 6144 + mt * 768);
#pragma unroll
                for (int p = 0; p < 2; p++)
                    LDSM4(b[2 * p][0], b[2 * p][1], b[2 * p + 1][0], b[2 * p + 1][1],
                          bB + ch * 6144 + p * 16 * 48);
#pragma unroll
                for (int mt = 0; mt < 4; mt++)
#pragma unroll
                    for (int nt = 0; nt < 4; nt++)
                        MMA16816(c[mt][nt][0], c[mt][nt][1], c[mt][nt][2], c[mt][nt][3],
                                 a[mt][0], a[mt][1], a[mt][2], a[mt][3],
                                 b[nt][0], b[nt][1]);
            }
            __syncthreads();
        }

        // epilogue
        float rsv[8], w2v[8], ncv[8];
        const int n2 = 2 * (l & 3);
#pragma unroll
        for (int nt = 0; nt < 4; nt++)
#pragma unroll
            for (int e = 0; e < 2; e++) {
                int n = nBase + warp_n * 32 + nt * 8 + n2 + e;
                rsv[nt * 2 + e] = g_rsum[n];
                w2v[nt * 2 + e] = g_w2[n];
                ncv[nt * 2 + e] = NC[n];
            }
#pragma unroll
        for (int mt = 0; mt < 4; mt++) {
#pragma unroll
            for (int hf = 0; hf < 2; hf++) {
                int brow = mBase + warp_m * 64 + mt * 16 + (l >> 2) + hf * 8;
                float x2v = g_x2[brow];
                __half* orow = g_acth + (size_t)brow * NN;
                float rmax = 0.f;
#pragma unroll
                for (int nt = 0; nt < 4; nt++) {
                    float act[2];
#pragma unroll
                    for (int e = 0; e < 2; e++) {
                        int i = nt * 2 + e;
                        float dot = c[mt][nt][hf * 2 + e];
                        float rs = rsv[i];
                        float dist = (x2v + w2v[i]) - 2.0f * dot;
                        float dw = dist * (rs * (1.0f / 1024.0f));
                        act[e] = rs / ((rs + dw) + 1e-7f) * ncv[i];
                        rmax = fmaxf(rmax, act[e]);
                    }
                    int n0 = nBase + warp_n * 32 + nt * 8 + n2;
                    __half2 ph = __floats2half2_rn(act[0], act[1]);
                    *(uint32_t*)(orow + n0) = *(uint32_t*)&ph;
                }
                rmax = fmaxf(rmax, __shfl_xor_sync(0xFFFFFFFFu, rmax, 1));
                rmax = fmaxf(rmax, __shfl_xor_sync(0xFFFFFFFFu, rmax, 2));
                if ((l & 3) == 0)
                    atomicMax(&g_rowmax[brow], __float_as_uint(rmax));
            }
        }
    } else {
        // ================= FFMA path (fp32 SIMT, R1-style) =================
        float* As = (float*)sm;               // [2][16][128]
        float* Bs = (float*)(sm + 16384);     // [2][16][128]
        const int tx = tid & 15, ty = tid >> 4;
        const int lrow = tid >> 1, lcol = (tid & 1) * 8;

        const float* xg = X + (size_t)(mBase + lrow) * DD + lcol;
        const float* wg = W + (size_t)(nBase + lrow) * DD + lcol;

        float4 xa = *(const float4*)(xg);
        float4 xb2 = *(const float4*)(xg + 4);
        float4 wa = *(const float4*)(wg);
        float4 wb2 = *(const float4*)(wg + 4);
#pragma unroll
        for (int c4 = 0; c4 < 4; c4++) {
            As[(lcol + c4) * 128 + lrow] = (&xa.x)[c4];
            As[(lcol + 4 + c4) * 128 + lrow] = (&xb2.x)[c4];
            Bs[(lcol + c4) * 128 + lrow] = (&wa.x)[c4];
            Bs[(lcol + 4 + c4) * 128 + lrow] = (&wb2.x)[c4];
        }
        __syncthreads();

        float acc[8][8];
#pragma unroll
        for (int i = 0; i < 8; i++)
#pragma unroll
            for (int j = 0; j < 8; j++) acc[i][j] = 0.f;

        const int NT = DD / 16;
        for (int t = 0; t < NT; t++) {
            const int cur = t & 1;
            if (t + 1 < NT) {
                const float* xg2 = xg + (t + 1) * 16;
                const float* wg2 = wg + (t + 1) * 16;
                xa = *(const float4*)(xg2);
                xb2 = *(const float4*)(xg2 + 4);
                wa = *(const float4*)(wg2);
                wb2 = *(const float4*)(wg2 + 4);
            }
            const float* Ac = As + cur * 2048;
            const float* Bc = Bs + cur * 2048;
#pragma unroll
            for (int k = 0; k < 16; k++) {
                float4 a0 = *(const float4*)&Ac[k * 128 + ty * 8];
                float4 a1 = *(const float4*)&Ac[k * 128 + ty * 8 + 4];
                float4 b0 = *(const float4*)&Bc[k * 128 + tx * 4];
                float4 b1 = *(const float4*)&Bc[k * 128 + 64 + tx * 4];
                float ar[8] = {a0.x, a0.y, a0.z, a0.w, a1.x, a1.y, a1.z, a1.w};
                float br[8] = {b0.x, b0.y, b0.z, b0.w, b1.x, b1.y, b1.z, b1.w};
#pragma unroll
                for (int i = 0; i < 8; i++)
#pragma unroll
                    for (int j = 0; j < 8; j++)
                        acc[i][j] = fmaf(ar[i], br[j], acc[i][j]);
            }
            if (t + 1 < NT) {
                const int nxt = cur ^ 1;
                float* An = As + nxt * 2048;
                float* Bn = Bs + nxt * 2048;
#pragma unroll
                for (int c4 = 0; c4 < 4; c4++) {
                    An[(lcol + c4) * 128 + lrow] = (&xa.x)[c4];
                    An[(lcol + 4 + c4) * 128 + lrow] = (&xb2.x)[c4];
                    Bn[(lcol + c4) * 128 + lrow] = (&wa.x)[c4];
                    Bn[(lcol + 4 + c4) * 128 + lrow] = (&wb2.x)[c4];
                }
            }
            __syncthreads();
        }

        // epilogue: acts (exact fp32), store fp16, rowmax via half-warp reduce
        int ncol[8];
        float rs[8], w2c[8], ncvv[8];
#pragma unroll
        for (int j = 0; j < 8; j++) {
            int n = nBase + ((j < 4) ? (tx * 4 + j) : (64 + tx * 4 + (j - 4)));
            ncol[j] = n;
            rs[j] = g_rsum[n];
            w2c[j] = g_w2[n];
            ncvv[j] = NC[n];
        }
#pragma unroll
        for (int i = 0; i < 8; i++) {
            const int brow = mBase + ty * 8 + i;
            const float x2v = g_x2[brow];
            __half* orow = g_acth + (size_t)brow * NN;
            float a[8];
            float rmax = 0.f;
#pragma unroll
            for (int j = 0; j < 8; j++) {
                float dist = (x2v + w2c[j]) - 2.0f * acc[i][j];
                float dw = dist * (rs[j] * (1.0f / 1024.0f));
                a[j] = rs[j] / ((rs[j] + dw) + 1e-7f) * ncvv[j];
                rmax = fmaxf(rmax, a[j]);
            }
            __half2 h01 = __floats2half2_rn(a[0], a[1]);
            __half2 h23 = __floats2half2_rn(a[2], a[3]);
            __half2 h45 = __floats2half2_rn(a[4], a[5]);
            __half2 h67 = __floats2half2_rn(a[6], a[7]);
            *(uint2*)(orow + ncol[0]) = make_uint2(*(uint32_t*)&h01, *(uint32_t*)&h23);
            *(uint2*)(orow + ncol[4]) = make_uint2(*(uint32_t*)&h45, *(uint32_t*)&h67);
            // reduce rmax over the 16 tx lanes (xor 1,2,4,8 stays within half-warp)
#pragma unroll
            for (int o = 1; o < 16; o <<= 1)
                rmax = fmaxf(rmax, __shfl_xor_sync(0xFFFFFFFFu, rmax, o));
            if (tx == 0)
                atomicMax(&g_rowmax[brow], __float_as_uint(rmax));
        }
    }
}

// ---------------------------------------------------------------------------
// K3a: candidate compaction, 4 rows/block, strided scan (R13)
// ---------------------------------------------------------------------------
__global__ void __launch_bounds__(256)
k_cand() {
    const int tid = threadIdx.x;
    const int b0 = blockIdx.x * 4;
    __shared__ float sthr[4];
    if (tid < 4) sthr[tid] = __uint_as_float(g_rowmax[b0 + tid]) - MARGIN;
    __syncthreads();

    const uint4* base = (const uint4*)(g_acth + (size_t)b0 * NN);
    uint4 v[8];
#pragma unroll
    for (int i = 0; i < 8; i++) v[i] = base[tid + i * 256];
#pragma unroll
    for (int i = 0; i < 8; i++) {
        const int idx = tid + i * 256;
        const int row = idx >> 9;
        const float thr = sthr[row];
        const int nb = (idx & 511) * 8;
        uint32_t ws[4] = {v[i].x, v[i].y, v[i].z, v[i].w};
#pragma unroll
        for (int q = 0; q < 4; q++) {
            __half2 h2 = *(__half2*)&ws[q];
            float a0 = __low2float(h2), a1 = __high2float(h2);
            if (a0 >= thr) {
                int p = atomicAdd(&g_ncand, 1);
                if (p < CAND_CAP)
                    g_cand[p] = ((unsigned)(b0 + row) << 12) | (unsigned)(nb + q * 2);
            }
            if (a1 >= thr) {
                int p = atomicAdd(&g_ncand, 1);
                if (p < CAND_CAP)
                    g_cand[p] = ((unsigned)(b0 + row) << 12) | (unsigned)(nb + q * 2 + 1);
            }
        }
    }
}

// ---------------------------------------------------------------------------
// K3b: exact fp32 rescore, one candidate per warp
// ---------------------------------------------------------------------------
__global__ void __launch_bounds__(256)
k_rescore(const float* __restrict__ X, const float* __restrict__ W,
          const float* __restrict__ NC) {
    const int l = threadIdx.x & 31;
    const int gw = blockIdx.x * 8 + (threadIdx.x >> 5);
    const int total = min(g_ncand, CAND_CAP);
    for (int ci = gw; ci < total; ci += gridDim.x * 8) {
        unsigned cd = g_cand[ci];
        int b = cd >> 12, n = cd & 4095;
        const float4* x4 = (const float4*)(X + (size_t)b * DD);
        const float4* w4 = (const float4*)(W + (size_t)n * DD);
        float p = 0.f;
#pragma unroll
        for (int j = 0; j < 8; j++) {
            float4 a = x4[l + j * 32], w = w4[l + j * 32];
            p += a.x * w.x + a.y * w.y + a.z * w.z + a.w * w.w;
        }
#pragma unroll
        for (int o = 16; o > 0; o >>= 1) p += __shfl_down_sync(0xFFFFFFFFu, p, o);
        if (l == 0) {
            float rs = g_rsum[n];
            float dist = (g_x2[b] + g_w2[n]) - 2.0f * p;
            float dw = dist * (rs * (1.0f / 1024.0f));
            float act = rs / ((rs + dw) + 1e-7f) * NC[n];
            unsigned long long kk =
                ((unsigned long long)__float_as_uint(act) << 32) |
                (unsigned int)(0xFFFFFFFFu - (unsigned int)n);
            atomicMax(&g_best[b], kk);
        }
    }
}

// ---------------------------------------------------------------------------
// K4: scatter
// ---------------------------------------------------------------------------
__global__ void k_scatter(const float* __restrict__ X, float* __restrict__ sums) {
    int b = blockIdx.x;
    unsigned long long key = g_best[b];
    float act = __uint_as_float((unsigned int)(key >> 32));
    if (!(act >= ATC)) return;
    int n = (int)(0xFFFFFFFFu - (unsigned int)key);
    if (threadIdx.x == 0) atomicAdd(&g_counts[n], 1.0f);
    const float* xr = X + (size_t)b * DD;
    float* sr = sums + (size_t)n * DD;
#pragma unroll
    for (int k = 0; k < 4; k++) {
        int d = threadIdx.x + k * 256;
        atomicAdd(&sr[d], xr[d]);
    }
}

// ---------------------------------------------------------------------------
// K5: finalize
// ---------------------------------------------------------------------------
__global__ void k_final(const float* __restrict__ W, const float* __restrict__ MAVG,
                        float* __restrict__ out) {
    int n = blockIdx.x;
    int tid = threadIdx.x;
    float cnt = g_counts[n];
    float has = (cnt > 0.f) ? 1.f : 0.f;
    float cmax = fmaxf(cnt, 1.f);

    float* out0 = out;
    float* out1 = out + (size_t)NN * DD;
    float* out2 = out + 2 * (size_t)NN * DD;

    float4 sv = ((const float4*)(out0 + (size_t)n * DD))[tid];
    float4 wv = ((const float4*)(W + (size_t)n * DD))[tid];
    float4 av = ((const float4*)(MAVG + (size_t)n * DD))[tid];

    float mean[4] = {sv.x / cmax, sv.y / cmax, sv.z / cmax, sv.w / cmax};
    float wr[4] = {wv.x, wv.y, wv.z, wv.w};
    float ma[4] = {av.x, av.y, av.z, av.w};
    float mvn[4];
    float lmax = -FLT_MAX, lmin = FLT_MAX, lsum = 0.f;
#pragma unroll
    for (int j = 0; j < 4; j++) {
        float dist = fabsf(mean[j] - wr[j]);
        mvn[j] = ACOEF * dist + (1.0f - ACOEF) * ma[j];
        lmax = fmaxf(lmax, mvn[j]);
        lmin = fminf(lmin, mvn[j]);
        lsum += mvn[j];
    }
#pragma unroll
    for (int o = 16; o > 0; o >>= 1) {
        lmax = fmaxf(lmax, __shfl_down_sync(0xFFFFFFFFu, lmax, o));
        lmin = fminf(lmin, __shfl_down_sync(0xFFFFFFFFu, lmin, o));
        lsum += __shfl_down_sync(0xFFFFFFFFu, lsum, o);
    }
    __shared__ float smx[8], smn[8], ssm[8];
    __shared__ float rmx, rmn, rsm;
    int w = tid >> 5, l = tid & 31;
    if (l == 0) { smx[w] = lmax; smn[w] = lmin; ssm[w] = lsum; }
    __syncthreads();
    if (tid == 0) {
        float a = -FLT_MAX, b2 = FLT_MAX, cc = 0.f;
#pragma unroll
        for (int i = 0; i < 8; i++) {
            a = fmaxf(a, smx[i]); b2 = fminf(b2, smn[i]); cc += ssm[i];
        }
        rmx = a; rmn = b2; rsm = cc;
    }
    __syncthreads();
    float avg = rsm * (1.0f / 1024.0f);
    float scale = EPSDS * (rmx - rmn);

    float r0[4], r1[4], r2[4];
#pragma unroll
    for (int j = 0; j < 4; j++) {
        float t = (mvn[j] - avg) / scale;
        float r = 1.0f / (1.0f + expf(t));
        if (r != r) r = 1.0f;
        r0[j] = mean[j] * has;
        r1[j] = (wr[j] + LRC * (mean[j] - wr[j])) * has;
        r2[j] = r * has;
    }
    ((float4*)(out0 + (size_t)n * DD))[tid] = make_float4(r0[0], r0[1], r0[2], r0[3]);
    ((float4*)(out1 + (size_t)n * DD))[tid] = make_float4(r1[0], r1[1], r1[2], r1[3]);
    ((float4*)(out2 + (size_t)n * DD))[tid] = make_float4(r2[0], r2[1], r2[2], r2[3]);
}

// ---------------------------------------------------------------------------
extern "C" void kernel_launch(void* const* d_in, const int* in_sizes, int n_in,
                              void* d_out, int out_size) {
    const float* x    = (const float*)d_in[0];
    const float* wts  = (const float*)d_in[1];
    const float* rel  = (const float*)d_in[2];
    const float* mavg = (const float*)d_in[3];
    const float* nc   = (const float*)d_in[4];
    float* out = (float*)d_out;

    cudaFuncSetAttribute(k_gemm_mixed, cudaFuncAttributeMaxDynamicSharedMemorySize, GEMM_SMEM);

    k_init<<<(NN * DD / 4) / 256, 256>>>((float4*)out);
    k_rowprep<<<(BB + NN) / 8, 256>>>(x, wts, rel);
    dim3 g(NN / 128, BB / 128);
    k_gemm_mixed<<<g, 256, GEMM_SMEM>>>(nc, x, wts);
    k_cand<<<BB / 4, 256>>>();
    k_rescore<<<512, 256>>>(x, wts, nc);
    k_scatter<<<BB, 256>>>(x, out);
    k_final<<<NN, 256>>>(wts, mavg, out);
}

// round 16
// speedup vs baseline: 1.6229x; 1.6229x over previous
#include <cuda_runtime.h>
#include <cuda_bf16.h>
#include <cuda_fp16.h>
#include <math.h>
#include <float.h>
#include <cstdint>

#define BB 8192
#define DD 1024
#define NN 4096
#define LRC 0.02f
#define ATC 0.3f
#define ACOEF 0.002f
#define EPSDS 0.5f
#define MARGIN 2e-3f
#define CAND_CAP (1 << 16)

// ---------------- device scratch ----------------
__device__ unsigned long long g_best[BB];
__device__ float g_x2[BB];
__device__ float g_w2[NN];
__device__ float g_rsum[NN];
__device__ float g_counts[NN];
__device__ unsigned int g_rowmax[BB];
__device__ int g_ncand;
__device__ unsigned int g_cand[CAND_CAP];
__device__ __nv_bfloat16 g_xb[BB * DD];       // 16 MB
__device__ __nv_bfloat16 g_wb[NN * DD];       // 8 MB
__device__ __half g_acth[(size_t)BB * NN];    // 32 MB fp16 acts

__device__ __forceinline__ uint32_t smem_u32(const void* p) {
    uint32_t a;
    asm("{ .reg .u64 t; cvta.to.shared.u64 t, %1; cvt.u32.u64 %0, t; }" : "=r"(a) : "l"(p));
    return a;
}

#define LDSM4(r0, r1, r2, r3, addr) \
    asm volatile("ldmatrix.sync.aligned.m8n8.x4.shared.b16 {%0,%1,%2,%3}, [%4];" \
                 : "=r"(r0), "=r"(r1), "=r"(r2), "=r"(r3) : "r"(addr))
#define MMA16816(c0, c1, c2, c3, a0, a1, a2, a3, b0, b1) \
    asm volatile("mma.sync.aligned.m16n8k16.row.col.f32.bf16.bf16.f32 " \
                 "{%0,%1,%2,%3}, {%4,%5,%6,%7}, {%8,%9}, {%0,%1,%2,%3};" \
                 : "+f"(c0), "+f"(c1), "+f"(c2), "+f"(c3) \
                 : "r"(a0), "r"(a1), "r"(a2), "r"(a3), "r"(b0), "r"(b1))
#define CPASYNC16(dst, src) \
    asm volatile("cp.async.ca.shared.global [%0], [%1], 16;" :: "r"(dst), "l"(src))
#define CPCOMMIT() asm volatile("cp.async.commit_group;" ::: "memory")
#define CPWAIT1() asm volatile("cp.async.wait_group 1;" ::: "memory")

static constexpr int STAGE_B = 24576;
static constexpr int GEMM_SMEM = 3 * STAGE_B;   // 73728

// ---------------------------------------------------------------------------
// K1: row reductions + bf16 conversion (warp per row) + fused init
//   grid = 1536 blocks; block bid also zeroes a slice of sums/counters first
// ---------------------------------------------------------------------------
__global__ void __launch_bounds__(256)
k_rowprep(const float* __restrict__ X, const float* __restrict__ W,
          const float* __restrict__ REL, float4* __restrict__ sums4) {
    const int tid = threadIdx.x;
    const int bid = blockIdx.x;          // 0..1535

    // ---- fused init: zero slices (stores overlap the loads below) ----
    // sums region: NN*DD/4 = 1,048,576 float4 over 1536 blocks x 256 thr
    {
        const int per = (NN * DD / 4 + 1536 * 256 - 1) / (1536 * 256);  // 3
        int base = (bid * 256 + tid) * per;
#pragma unroll
        for (int i = 0; i < 3; i++) {
            int idx = base + i;
            if (idx < NN * DD / 4) sums4[idx] = make_float4(0.f, 0.f, 0.f, 0.f);
        }
        int gi = bid * 256 + tid;
        if (gi < NN) g_counts[gi] = 0.f;
        if (gi < BB) { g_rowmax[gi] = 0u; g_best[gi] = 0ull; }
        if (gi == 0) g_ncand = 0;
    }

    const int wid = tid >> 5, l = tid & 31;
    const int r = bid * 8 + wid;
    float v1 = 0.f, v2 = 0.f;
    if (r < BB) {
        const float4* xr = (const float4*)(X + (size_t)r * DD);
        uint2* ob = (uint2*)(g_xb + (size_t)r * DD);
#pragma unroll
        for (int j = 0; j < 8; j++) {
            float4 v = xr[l + j * 32];
            v1 += v.x * v.x + v.y * v.y + v.z * v.z + v.w * v.w;
            __nv_bfloat162 p0 = __floats2bfloat162_rn(v.x, v.y);
            __nv_bfloat162 p1 = __floats2bfloat162_rn(v.z, v.w);
            ob[l + j * 32] = make_uint2(*(uint32_t*)&p0, *(uint32_t*)&p1);
        }
    } else {
        const int n = r - BB;
        const float4* wr = (const float4*)(W + (size_t)n * DD);
        const float4* rr = (const float4*)(REL + (size_t)n * DD);
        uint2* ob = (uint2*)(g_wb + (size_t)n * DD);
#pragma unroll
        for (int j = 0; j < 8; j++) {
            float4 v = wr[l + j * 32];
            float4 rv = rr[l + j * 32];
            v1 += v.x * v.x + v.y * v.y + v.z * v.z + v.w * v.w;
            v2 += rv.x + rv.y + rv.z + rv.w;
            __nv_bfloat162 p0 = __floats2bfloat162_rn(v.x, v.y);
            __nv_bfloat162 p1 = __floats2bfloat162_rn(v.z, v.w);
            ob[l + j * 32] = make_uint2(*(uint32_t*)&p0, *(uint32_t*)&p1);
        }
    }
#pragma unroll
    for (int o = 16; o > 0; o >>= 1) {
        v1 += __shfl_down_sync(0xFFFFFFFFu, v1, o);
        v2 += __shfl_down_sync(0xFFFFFFFFu, v2, o);
    }
    if (l == 0) {
        if (r < BB) g_x2[r] = v1;
        else { g_w2[r - BB] = v1; g_rsum[r - BB] = v2; }
    }
}

// ---------------------------------------------------------------------------
// K2: bf16 mma.sync GEMM (128x128 tile, 3-stage cp.async)
//     epilogue -> fp16 acts + rowmax   (R13, measured best)
// ---------------------------------------------------------------------------
__global__ void __launch_bounds__(256, 2)
k_gemm_bf16(const float* __restrict__ NC) {
    extern __shared__ __align__(128) char sm[];
    const uint32_t sb = smem_u32(sm);

    const int tid = threadIdx.x;
    const int l = tid & 31, wid = tid >> 5;
    const int warp_m = wid >> 2, warp_n = wid & 3;
    const int mBase = blockIdx.y * 128;
    const int nBase = blockIdx.x * 128;

    const int row = tid >> 1, h = tid & 1;
    const __nv_bfloat16* xg = g_xb + (size_t)(mBase + row) * DD + h * 16;
    const __nv_bfloat16* wg = g_wb + (size_t)(nBase + row) * DD + h * 16;
    const uint32_t aDst = sb + h * 6144 + row * 48;
    const uint32_t bDst = sb + 12288 + h * 6144 + row * 48;

#pragma unroll
    for (int s = 0; s < 2; s++) {
        const __nv_bfloat16* xs = xg + s * 32;
        const __nv_bfloat16* ws = wg + s * 32;
        CPASYNC16(aDst + s * STAGE_B, xs);
        CPASYNC16(aDst + s * STAGE_B + 16, xs + 8);
        CPASYNC16(bDst + s * STAGE_B, ws);
        CPASYNC16(bDst + s * STAGE_B + 16, ws + 8);
        CPCOMMIT();
    }

    float c[4][4][4];
#pragma unroll
    for (int i = 0; i < 4; i++)
#pragma unroll
        for (int j = 0; j < 4; j++)
#pragma unroll
            for (int k = 0; k < 4; k++) c[i][j][k] = 0.f;

    const uint32_t aAddr0 = sb + (warp_m * 64 + (l & 15)) * 48 + (l >> 4) * 16;
    const int b_nt_off = (l >> 4) & 1;
    const int b_half = (l >> 3) & 1;
    const uint32_t bAddr0 = sb + 12288 +
        (warp_n * 32 + b_nt_off * 8 + (l & 7)) * 48 + b_half * 16;

    for (int kt = 0; kt < 32; kt++) {
        CPWAIT1();
        __syncthreads();
        if (kt + 2 < 32) {
            const int s = (kt + 2) % 3;
            const __nv_bfloat16* xs = xg + (kt + 2) * 32;
            const __nv_bfloat16* ws = wg + (kt + 2) * 32;
            CPASYNC16(aDst + s * STAGE_B, xs);
            CPASYNC16(aDst + s * STAGE_B + 16, xs + 8);
            CPASYNC16(bDst + s * STAGE_B, ws);
            CPASYNC16(bDst + s * STAGE_B + 16, ws + 8);
        }
        CPCOMMIT();

        const uint32_t aB = aAddr0 + (kt % 3) * STAGE_B;
        const uint32_t bB = bAddr0 + (kt % 3) * STAGE_B;
#pragma unroll
        for (int ch = 0; ch < 2; ch++) {
            uint32_t a[4][4], b[4][2];
#pragma unroll
            for (int mt = 0; mt < 4; mt++)
                LDSM4(a[mt][0], a[mt][1], a[mt][2], a[mt][3], aB + ch * 6144 + mt * 768);
#pragma unroll
            for (int p = 0; p < 2; p++)
                LDSM4(b[2 * p][0], b[2 * p][1], b[2 * p + 1][0], b[2 * p + 1][1],
                      bB + ch * 6144 + p * 16 * 48);
#pragma unroll
            for (int mt = 0; mt < 4; mt++)
#pragma unroll
                for (int nt = 0; nt < 4; nt++)
                    MMA16816(c[mt][nt][0], c[mt][nt][1], c[mt][nt][2], c[mt][nt][3],
                             a[mt][0], a[mt][1], a[mt][2], a[mt][3],
                             b[nt][0], b[nt][1]);
        }
        __syncthreads();
    }

    // ---- epilogue: act -> fp16 g_acth + rowmax ----
    float rsv[8], w2v[8], ncv[8];
    const int n2 = 2 * (l & 3);
#pragma unroll
    for (int nt = 0; nt < 4; nt++)
#pragma unroll
        for (int e = 0; e < 2; e++) {
            int n = nBase + warp_n * 32 + nt * 8 + n2 + e;
            rsv[nt * 2 + e] = g_rsum[n];
            w2v[nt * 2 + e] = g_w2[n];
            ncv[nt * 2 + e] = NC[n];
        }
#pragma unroll
    for (int mt = 0; mt < 4; mt++) {
#pragma unroll
        for (int hf = 0; hf < 2; hf++) {
            int brow = mBase + warp_m * 64 + mt * 16 + (l >> 2) + hf * 8;
            float x2v = g_x2[brow];
            __half* orow = g_acth + (size_t)brow * NN;
            float rmax = 0.f;
#pragma unroll
            for (int nt = 0; nt < 4; nt++) {
                float act[2];
#pragma unroll
                for (int e = 0; e < 2; e++) {
                    int i = nt * 2 + e;
                    float dot = c[mt][nt][hf * 2 + e];
                    float rs = rsv[i];
                    float dist = (x2v + w2v[i]) - 2.0f * dot;
                    float dw = dist * (rs * (1.0f / 1024.0f));
                    act[e] = rs / ((rs + dw) + 1e-7f) * ncv[i];
                    rmax = fmaxf(rmax, act[e]);
                }
                int n0 = nBase + warp_n * 32 + nt * 8 + n2;
                __half2 ph = __floats2half2_rn(act[0], act[1]);
                *(uint32_t*)(orow + n0) = *(uint32_t*)&ph;
            }
            rmax = fmaxf(rmax, __shfl_xor_sync(0xFFFFFFFFu, rmax, 1));
            rmax = fmaxf(rmax, __shfl_xor_sync(0xFFFFFFFFu, rmax, 2));
            if ((l & 3) == 0)
                atomicMax(&g_rowmax[brow], __float_as_uint(rmax));
        }
    }
}

// ---------------------------------------------------------------------------
// K3a: candidate compaction, block per row (R8 measured-best shape)
// ---------------------------------------------------------------------------
__global__ void __launch_bounds__(256)
k_cand() {
    const int b = blockIdx.x;
    const float thr = __uint_as_float(g_rowmax[b]) - MARGIN;
    const uint4* p = (const uint4*)(g_acth + (size_t)b * NN);
    uint4 v0 = p[threadIdx.x];
    uint4 v1 = p[threadIdx.x + 256];
#pragma unroll
    for (int it = 0; it < 2; it++) {
        uint4 v = it ? v1 : v0;
        int idx = threadIdx.x + it * 256;
        uint32_t ws[4] = {v.x, v.y, v.z, v.w};
#pragma unroll
        for (int q = 0; q < 4; q++) {
            __half2 h2 = *(__half2*)&ws[q];
            float a0 = __low2float(h2), a1 = __high2float(h2);
            if (a0 >= thr) {
                int pos = atomicAdd(&g_ncand, 1);
                if (pos < CAND_CAP)
                    g_cand[pos] = ((unsigned)b << 12) | (unsigned)(idx * 8 + q * 2);
            }
            if (a1 >= thr) {
                int pos = atomicAdd(&g_ncand, 1);
                if (pos < CAND_CAP)
                    g_cand[pos] = ((unsigned)b << 12) | (unsigned)(idx * 8 + q * 2 + 1);
            }
        }
    }
}

// ---------------------------------------------------------------------------
// K3b: exact fp32 rescore, one candidate per warp
// ---------------------------------------------------------------------------
__global__ void __launch_bounds__(256)
k_rescore(const float* __restrict__ X, const float* __restrict__ W,
          const float* __restrict__ NC) {
    const int l = threadIdx.x & 31;
    const int gw = blockIdx.x * 8 + (threadIdx.x >> 5);
    const int total = min(g_ncand, CAND_CAP);
    for (int ci = gw; ci < total; ci += gridDim.x * 8) {
        unsigned cd = g_cand[ci];
        int b = cd >> 12, n = cd & 4095;
        const float4* x4 = (const float4*)(X + (size_t)b * DD);
        const float4* w4 = (const float4*)(W + (size_t)n * DD);
        float p = 0.f;
#pragma unroll
        for (int j = 0; j < 8; j++) {
            float4 a = x4[l + j * 32], w = w4[l + j * 32];
            p += a.x * w.x + a.y * w.y + a.z * w.z + a.w * w.w;
        }
#pragma unroll
        for (int o = 16; o > 0; o >>= 1) p += __shfl_down_sync(0xFFFFFFFFu, p, o);
        if (l == 0) {
            float rs = g_rsum[n];
            float dist = (g_x2[b] + g_w2[n]) - 2.0f * p;
            float dw = dist * (rs * (1.0f / 1024.0f));
            float act = rs / ((rs + dw) + 1e-7f) * NC[n];
            unsigned long long kk =
                ((unsigned long long)__float_as_uint(act) << 32) |
                (unsigned int)(0xFFFFFFFFu - (unsigned int)n);
            atomicMax(&g_best[b], kk);
        }
    }
}

// ---------------------------------------------------------------------------
// K4: scatter
// ---------------------------------------------------------------------------
__global__ void k_scatter(const float* __restrict__ X, float* __restrict__ sums) {
    int b = blockIdx.x;
    unsigned long long key = g_best[b];
    float act = __uint_as_float((unsigned int)(key >> 32));
    if (!(act >= ATC)) return;
    int n = (int)(0xFFFFFFFFu - (unsigned int)key);
    if (threadIdx.x == 0) atomicAdd(&g_counts[n], 1.0f);
    const float* xr = X + (size_t)b * DD;
    float* sr = sums + (size_t)n * DD;
#pragma unroll
    for (int k = 0; k < 4; k++) {
        int d = threadIdx.x + k * 256;
        atomicAdd(&sr[d], xr[d]);
    }
}

// ---------------------------------------------------------------------------
// K5: finalize
// ---------------------------------------------------------------------------
__global__ void k_final(const float* __restrict__ W, const float* __restrict__ MAVG,
                        float* __restrict__ out) {
    int n = blockIdx.x;
    int tid = threadIdx.x;
    float cnt = g_counts[n];
    float has = (cnt > 0.f) ? 1.f : 0.f;
    float cmax = fmaxf(cnt, 1.f);

    float* out0 = out;
    float* out1 = out + (size_t)NN * DD;
    float* out2 = out + 2 * (size_t)NN * DD;

    float4 sv = ((const float4*)(out0 + (size_t)n * DD))[tid];
    float4 wv = ((const float4*)(W + (size_t)n * DD))[tid];
    float4 av = ((const float4*)(MAVG + (size_t)n * DD))[tid];

    float mean[4] = {sv.x / cmax, sv.y / cmax, sv.z / cmax, sv.w / cmax};
    float wr[4] = {wv.x, wv.y, wv.z, wv.w};
    float ma[4] = {av.x, av.y, av.z, av.w};
    float mvn[4];
    float lmax = -FLT_MAX, lmin = FLT_MAX, lsum = 0.f;
#pragma unroll
    for (int j = 0; j < 4; j++) {
        float dist = fabsf(mean[j] - wr[j]);
        mvn[j] = ACOEF * dist + (1.0f - ACOEF) * ma[j];
        lmax = fmaxf(lmax, mvn[j]);
        lmin = fminf(lmin, mvn[j]);
        lsum += mvn[j];
    }
#pragma unroll
    for (int o = 16; o > 0; o >>= 1) {
        lmax = fmaxf(lmax, __shfl_down_sync(0xFFFFFFFFu, lmax, o));
        lmin = fminf(lmin, __shfl_down_sync(0xFFFFFFFFu, lmin, o));
        lsum += __shfl_down_sync(0xFFFFFFFFu, lsum, o);
    }
    __shared__ float smx[8], smn[8], ssm[8];
    __shared__ float rmx, rmn, rsm;
    int w = tid >> 5, l = tid & 31;
    if (l == 0) { smx[w] = lmax; smn[w] = lmin; ssm[w] = lsum; }
    __syncthreads();
    if (tid == 0) {
        float a = -FLT_MAX, b2 = FLT_MAX, cc = 0.f;
#pragma unroll
        for (int i = 0; i < 8; i++) {
            a = fmaxf(a, smx[i]); b2 = fminf(b2, smn[i]); cc += ssm[i];
        }
        rmx = a; rmn = b2; rsm = cc;
    }
    __syncthreads();
    float avg = rsm * (1.0f / 1024.0f);
    float scale = EPSDS * (rmx - rmn);

    float r0[4], r1[4], r2[4];
#pragma unroll
    for (int j = 0; j < 4; j++) {
        float t = (mvn[j] - avg) / scale;
        float r = 1.0f / (1.0f + expf(t));
        if (r != r) r = 1.0f;
        r0[j] = mean[j] * has;
        r1[j] = (wr[j] + LRC * (mean[j] - wr[j])) * has;
        r2[j] = r * has;
    }
    ((float4*)(out0 + (size_t)n * DD))[tid] = make_float4(r0[0], r0[1], r0[2], r0[3]);
    ((float4*)(out1 + (size_t)n * DD))[tid] = make_float4(r1[0], r1[1], r1[2], r1[3]);
    ((float4*)(out2 + (size_t)n * DD))[tid] = make_float4(r2[0], r2[1], r2[2], r2[3]);
}

// ---------------------------------------------------------------------------
extern "C" void kernel_launch(void* const* d_in, const int* in_sizes, int n_in,
                              void* d_out, int out_size) {
    const float* x    = (const float*)d_in[0];
    const float* wts  = (const float*)d_in[1];
    const float* rel  = (const float*)d_in[2];
    const float* mavg = (const float*)d_in[3];
    const float* nc   = (const float*)d_in[4];
    float* out = (float*)d_out;

    cudaFuncSetAttribute(k_gemm_bf16, cudaFuncAttributeMaxDynamicSharedMemorySize, GEMM_SMEM);

    k_rowprep<<<(BB + NN) / 8, 256>>>(x, wts, rel, (float4*)out);
    dim3 g(NN / 128, BB / 128);
    k_gemm_bf16<<<g, 256, GEMM_SMEM>>>(nc);
    k_cand<<<BB, 256>>>();
    k_rescore<<<512, 256>>>(x, wts, nc);
    k_scatter<<<BB, 256>>>(x, out);
    k_final<<<NN, 256>>>(wts, mavg, out);
}